// round 1
// baseline (speedup 1.0000x reference)
#include <cuda_runtime.h>

// iPUNet forward, fully fused. One CTA per point (BN = 2*1024 = 2048).
//
// Fixed shapes (from setup_inputs):
//   B=2, N=1024, FEAT=128, NSAMPLE=48, GRID=7, RADIUS=0.3
// Inputs (metadata order):
//   0 xyz      (2,3,1024)    f32   6144
//   1 pts_feat (2,1024,128)  f32   262144
//   2 W0       (3,128)       f32   384
//   3 b0       (3,)          f32   3
//   4 W1       (3,128)       f32   384
//   5 b1       (3,)          f32   3
//   6 W_unet   (128,7,3)     f32   2688
//   7 index    (16,)         i32   16
// Output (f32, concatenated tuple, 417792 elems):
//   oris       [0      , 6144)    (B,N,3)
//   nors       [6144   , 12288)   (B,N,3)
//   pts_ups    [12288  , 110592)  (B,N*16,3)
//   pts_offset [110592 , 116736)  (B,N,3)
//   pts_up     [116736 , 417792)  (B*N,49,3)

#define NPTS   1024
#define FEATD  128
#define NS     48

#define OFF_ORIS   0
#define OFF_NORS   6144
#define OFF_UPS    12288
#define OFF_OFFSET 110592
#define OFF_PTSUP  116736

__device__ __forceinline__ float wredf(float x) {
#pragma unroll
    for (int o = 16; o; o >>= 1) x += __shfl_xor_sync(0xffffffffu, x, o);
    return x;
}

__global__ __launch_bounds__(256)
void ipunet_kernel(const float* __restrict__ xyz,
                   const float* __restrict__ feat,
                   const float* __restrict__ W0, const float* __restrict__ b0,
                   const float* __restrict__ W1, const float* __restrict__ b1,
                   const float* __restrict__ Wu, const int* __restrict__ g_index,
                   float* __restrict__ out)
{
    const int p    = blockIdx.x;       // 0..2047 (global point id)
    const int b    = p >> 10;          // batch
    const int t    = threadIdx.x;
    const int lane = t & 31;
    const int warp = t >> 5;

    __shared__ float    s_wu[FEATD * 7 * 3];   // W_unet cached (10.5 KB)
    __shared__ float    s_rot[9];              // rows: ori_0, ori_rot90, nors
    __shared__ float    s_center[3];
    __shared__ float    s_c2;
    __shared__ float    s_part[4][6];
    __shared__ unsigned s_mask[32];            // 1024-bit in-ball mask
    __shared__ int      s_nbr[NS];
    __shared__ int      s_cell[NS];
    __shared__ int      s_win[91];             // cell -> winning sample (max s)
    __shared__ int      s_cnt;
    __shared__ float    s_off[49 * 3];
    __shared__ int      s_idx[16];

    // ---- init / cooperative loads --------------------------------------
    for (int i = t; i < FEATD * 7 * 3; i += 256) s_wu[i] = Wu[i];
    if (t < 3)      s_center[t] = xyz[b * 3 * NPTS + t * NPTS + (p & 1023)];
    if (t < 16)     s_idx[t]    = g_index[t];
    if (t < 91)     s_win[t]    = -1;
    if (t < 49 * 3) s_off[t]    = 0.0f;

    // ---- oris / nors matvecs (feat row dot 6 weight rows) ---------------
    float q0 = 0.f, q1 = 0.f, q2 = 0.f, q3 = 0.f, q4 = 0.f, q5 = 0.f;
    if (t < FEATD) {
        float f = feat[(p << 7) + t];
        q0 = f * W0[t]; q1 = f * W0[128 + t]; q2 = f * W0[256 + t];
        q3 = f * W1[t]; q4 = f * W1[128 + t]; q5 = f * W1[256 + t];
    }
    if (warp < 4) {
        q0 = wredf(q0); q1 = wredf(q1); q2 = wredf(q2);
        q3 = wredf(q3); q4 = wredf(q4); q5 = wredf(q5);
        if (lane == 0) {
            s_part[warp][0] = q0; s_part[warp][1] = q1; s_part[warp][2] = q2;
            s_part[warp][3] = q3; s_part[warp][4] = q4; s_part[warp][5] = q5;
        }
    }
    __syncthreads();

    if (t == 0) {
        float ov[3], nv[3];
#pragma unroll
        for (int d = 0; d < 3; d++) {
            ov[d] = s_part[0][d] + s_part[1][d] + s_part[2][d] + s_part[3][d] + b0[d];
            nv[d] = s_part[0][3 + d] + s_part[1][3 + d] + s_part[2][3 + d] + s_part[3][3 + d] + b1[d];
        }
        // batch_norm: x / (sqrt(sum(x*x)+1e-8) + 1e-10)
        float so = ov[0]*ov[0] + ov[1]*ov[1] + ov[2]*ov[2];
        float io = 1.0f / (sqrtf(so + 1e-8f) + 1e-10f);
        ov[0] *= io; ov[1] *= io; ov[2] *= io;
        float sn = nv[0]*nv[0] + nv[1]*nv[1] + nv[2]*nv[2];
        float in = 1.0f / (sqrtf(sn + 1e-8f) + 1e-10f);
        nv[0] *= in; nv[1] *= in; nv[2] *= in;

        // ori_rot90 = norm(cross(oris, nors))
        float r90[3];
        r90[0] = ov[1]*nv[2] - ov[2]*nv[1];
        r90[1] = ov[2]*nv[0] - ov[0]*nv[2];
        r90[2] = ov[0]*nv[1] - ov[1]*nv[0];
        float sr = r90[0]*r90[0] + r90[1]*r90[1] + r90[2]*r90[2];
        float ir = 1.0f / (sqrtf(sr + 1e-8f) + 1e-10f);
        r90[0] *= ir; r90[1] *= ir; r90[2] *= ir;

        // ori_0 = norm(cross(ori_rot90, nors))
        float o0[3];
        o0[0] = r90[1]*nv[2] - r90[2]*nv[1];
        o0[1] = r90[2]*nv[0] - r90[0]*nv[2];
        o0[2] = r90[0]*nv[1] - r90[1]*nv[0];
        float s0 = o0[0]*o0[0] + o0[1]*o0[1] + o0[2]*o0[2];
        float i0 = 1.0f / (sqrtf(s0 + 1e-8f) + 1e-10f);
        o0[0] *= i0; o0[1] *= i0; o0[2] *= i0;

        s_rot[0] = o0[0];  s_rot[1] = o0[1];  s_rot[2] = o0[2];
        s_rot[3] = r90[0]; s_rot[4] = r90[1]; s_rot[5] = r90[2];
        s_rot[6] = nv[0];  s_rot[7] = nv[1];  s_rot[8] = nv[2];

#pragma unroll
        for (int d = 0; d < 3; d++) {
            out[OFF_ORIS + p * 3 + d] = ov[d];
            out[OFF_NORS + p * 3 + d] = nv[d];
        }
        s_c2 = s_center[0]*s_center[0] + s_center[1]*s_center[1] + s_center[2]*s_center[2];
    }
    __syncthreads();

    // ---- ball query: 1024-bit mask via ballot ---------------------------
    const float cx = s_center[0], cy = s_center[1], cz = s_center[2];
    const float c2 = s_c2;
    const float* xb = xyz + b * 3 * NPTS;
#pragma unroll
    for (int seg = 0; seg < 4; seg++) {
        int j = seg * 256 + t;
        float px = xb[j], py = xb[NPTS + j], pz = xb[2 * NPTS + j];
        float dot = cx * px + cy * py + cz * pz;
        float d = -2.0f * dot + c2 + (px * px + py * py + pz * pz);
        unsigned m = __ballot_sync(0xffffffffu, !(d > 0.09f));
        if (lane == 0) s_mask[seg * 8 + warp] = m;
    }
    __syncthreads();

    // ---- extract first <=48 set bits in ascending index order (warp 0) --
    if (warp == 0) {
        unsigned m = s_mask[lane];
        int pc = __popc(m);
        int incl = pc;
#pragma unroll
        for (int o = 1; o < 32; o <<= 1) {
            int v = __shfl_up_sync(0xffffffffu, incl, o);
            if (lane >= o) incl += v;
        }
        int excl = incl - pc;
        if (lane == 31) s_cnt = (incl < NS) ? incl : NS;
        unsigned mm = m;
        int r = excl;
        while (mm && r < NS) {
            int bpos = __ffs(mm) - 1;
            s_nbr[r] = (lane << 5) + bpos;
            mm &= mm - 1;
            r++;
        }
    }
    __syncthreads();

    // ---- pad, local coords, cell index, last-wins winner ----------------
    if (t < NS) {
        int j = (t < s_cnt) ? s_nbr[t] : s_nbr[0];
        s_nbr[t] = j;
        float lx = xb[j] - cx, ly = xb[NPTS + j] - cy, lz = xb[2 * NPTS + j] - cz;
        int c[3];
#pragma unroll
        for (int d = 0; d < 3; d++) {
            float lp = lx * s_rot[d * 3 + 0] + ly * s_rot[d * 3 + 1] + lz * s_rot[d * 3 + 2];
            float v = rintf((lp + 0.3f) / 0.6f * 6.0f);
            int ci = (int)v;
            ci = ci < 0 ? 0 : (ci > 6 ? 6 : ci);
            c[d] = ci;
        }
        int cell = c[0] * 7 + c[1] * 7 + c[2];   // reference quirk: both *g
        s_cell[t] = cell;
        atomicMax(&s_win[cell], t);
    }
    __syncthreads();

    // ---- sparse feat_off: per winning cell, 128-dot x3 against W_unet ---
    for (int s = warp; s < NS; s += 8) {
        int cell = s_cell[s];
        if (s_win[cell] != s) continue;          // warp-uniform
        const float* f = feat + (((b << 10) + s_nbr[s]) << 7);
        int k  = cell % 7;
        int p5 = (cell / 49) * 7 + (cell / 7) % 7;
        float a0 = 0.f, a1 = 0.f, a2 = 0.f;
#pragma unroll
        for (int c = lane; c < FEATD; c += 32) {
            float v = f[c];
            const float* wb = &s_wu[c * 21 + k * 3];
            a0 += v * wb[0]; a1 += v * wb[1]; a2 += v * wb[2];
        }
        a0 = wredf(a0); a1 = wredf(a1); a2 = wredf(a2);
        if (lane == 0) {
            atomicAdd(&s_off[p5 * 3 + 0], a0);
            atomicAdd(&s_off[p5 * 3 + 1], a1);
            atomicAdd(&s_off[p5 * 3 + 2], a2);
        }
    }
    __syncthreads();

    // ---- up = vals + feat_off; rotate back to world; write outputs ------
    if (t < 49) {
        int s = t;
        float u0 = (float)(s / 7 - 3) * 0.1f + s_off[s * 3 + 0];
        float u1 = (float)(s % 7 - 3) * 0.1f + s_off[s * 3 + 1];
        float u2 = s_off[s * 3 + 2];
        float w[3];
#pragma unroll
        for (int d = 0; d < 3; d++)
            w[d] = u0 * s_rot[d] + u1 * s_rot[3 + d] + u2 * s_rot[6 + d] + s_center[d];

        float* o_up = out + OFF_PTSUP + (p * 49 + s) * 3;
        o_up[0] = w[0]; o_up[1] = w[1]; o_up[2] = w[2];

        if (s == 24) {
            float* o_of = out + OFF_OFFSET + p * 3;
            o_of[0] = w[0]; o_of[1] = w[1]; o_of[2] = w[2];
        }
#pragma unroll
        for (int q = 0; q < 16; q++) {
            if (s_idx[q] == s) {
                float* o_u = out + OFF_UPS + (p * 16 + q) * 3;
                o_u[0] = w[0]; o_u[1] = w[1]; o_u[2] = w[2];
            }
        }
    }
}

extern "C" void kernel_launch(void* const* d_in, const int* in_sizes, int n_in,
                              void* d_out, int out_size)
{
    const float* xyz   = (const float*)d_in[0];
    const float* feat  = (const float*)d_in[1];
    const float* W0    = (const float*)d_in[2];
    const float* b0    = (const float*)d_in[3];
    const float* W1    = (const float*)d_in[4];
    const float* b1    = (const float*)d_in[5];
    const float* Wu    = (const float*)d_in[6];
    const int*   index = (const int*)d_in[7];
    float* out = (float*)d_out;

    ipunet_kernel<<<2048, 256>>>(xyz, feat, W0, b0, W1, b1, Wu, index, out);
}

// round 2
// speedup vs baseline: 1.5000x; 1.5000x over previous
#include <cuda_runtime.h>

// iPUNet forward, fully fused. One CTA (128 threads) per point, BN=2048 CTAs.
// Single-wave design: smem ~1.7KB, 128 thr -> 16 CTAs/SM -> all 2048 CTAs
// resident at once on 148 SMs.
//
// Shapes: B=2, N=1024, FEAT=128, NSAMPLE=48, GRID=7, RADIUS=0.3
// Output (f32, 417792 elems):
//   oris       [0      , 6144)
//   nors       [6144   , 12288)
//   pts_ups    [12288  , 110592)
//   pts_offset [110592 , 116736)
//   pts_up     [116736 , 417792)

#define NPTS   1024
#define FEATD  128
#define NS     48

#define OFF_ORIS   0
#define OFF_NORS   6144
#define OFF_UPS    12288
#define OFF_OFFSET 110592
#define OFF_PTSUP  116736

__device__ __forceinline__ float wredf(float x) {
#pragma unroll
    for (int o = 16; o; o >>= 1) x += __shfl_xor_sync(0xffffffffu, x, o);
    return x;
}

__global__ __launch_bounds__(128)
void ipunet_kernel(const float* __restrict__ xyz,
                   const float* __restrict__ feat,
                   const float* __restrict__ W0, const float* __restrict__ b0,
                   const float* __restrict__ W1, const float* __restrict__ b1,
                   const float* __restrict__ Wu, const int* __restrict__ g_index,
                   float* __restrict__ out)
{
    const int p    = blockIdx.x;       // 0..2047 (global point id)
    const int b    = p >> 10;          // batch
    const int t    = threadIdx.x;      // 0..127
    const int lane = t & 31;
    const int warp = t >> 5;           // 0..3

    __shared__ float    s_rot[9];              // rows: ori_0, ori_rot90, nors
    __shared__ float    s_center[3];
    __shared__ float    s_c2;
    __shared__ float    s_part[4][6];
    __shared__ unsigned s_mask[32];            // 1024-bit in-ball mask
    __shared__ int      s_nbr[NS];
    __shared__ int      s_cell[NS];
    __shared__ int      s_win[91];             // cell -> winning sample (max s)
    __shared__ int      s_cnt;
    __shared__ float    s_off[49 * 3];
    __shared__ int      s_idx[16];

    // ---- init ------------------------------------------------------------
    if (t < 3)  s_center[t] = xyz[b * 3 * NPTS + t * NPTS + (p & 1023)];
    if (t < 16) s_idx[t]    = g_index[t];
    if (t < 91) s_win[t]    = -1;
    if (t >= 91 && t < 107) ;            // (no-op; keep thread divergence simple)
    for (int i = t; i < 49 * 3; i += 128) s_off[i] = 0.0f;

    // ---- oris / nors matvecs (feat row dot 6 weight rows) -----------------
    {
        float f = __ldg(&feat[(p << 7) + t]);
        float q0 = f * __ldg(&W0[t]);
        float q1 = f * __ldg(&W0[128 + t]);
        float q2 = f * __ldg(&W0[256 + t]);
        float q3 = f * __ldg(&W1[t]);
        float q4 = f * __ldg(&W1[128 + t]);
        float q5 = f * __ldg(&W1[256 + t]);
        q0 = wredf(q0); q1 = wredf(q1); q2 = wredf(q2);
        q3 = wredf(q3); q4 = wredf(q4); q5 = wredf(q5);
        if (lane == 0) {
            s_part[warp][0] = q0; s_part[warp][1] = q1; s_part[warp][2] = q2;
            s_part[warp][3] = q3; s_part[warp][4] = q4; s_part[warp][5] = q5;
        }
    }
    __syncthreads();

    if (t == 0) {
        float ov[3], nv[3];
#pragma unroll
        for (int d = 0; d < 3; d++) {
            ov[d] = s_part[0][d] + s_part[1][d] + s_part[2][d] + s_part[3][d] + __ldg(&b0[d]);
            nv[d] = s_part[0][3 + d] + s_part[1][3 + d] + s_part[2][3 + d] + s_part[3][3 + d] + __ldg(&b1[d]);
        }
        float so = ov[0]*ov[0] + ov[1]*ov[1] + ov[2]*ov[2];
        float io = 1.0f / (sqrtf(so + 1e-8f) + 1e-10f);
        ov[0] *= io; ov[1] *= io; ov[2] *= io;
        float sn = nv[0]*nv[0] + nv[1]*nv[1] + nv[2]*nv[2];
        float in = 1.0f / (sqrtf(sn + 1e-8f) + 1e-10f);
        nv[0] *= in; nv[1] *= in; nv[2] *= in;

        float r90[3];
        r90[0] = ov[1]*nv[2] - ov[2]*nv[1];
        r90[1] = ov[2]*nv[0] - ov[0]*nv[2];
        r90[2] = ov[0]*nv[1] - ov[1]*nv[0];
        float sr = r90[0]*r90[0] + r90[1]*r90[1] + r90[2]*r90[2];
        float ir = 1.0f / (sqrtf(sr + 1e-8f) + 1e-10f);
        r90[0] *= ir; r90[1] *= ir; r90[2] *= ir;

        float o0[3];
        o0[0] = r90[1]*nv[2] - r90[2]*nv[1];
        o0[1] = r90[2]*nv[0] - r90[0]*nv[2];
        o0[2] = r90[0]*nv[1] - r90[1]*nv[0];
        float s0 = o0[0]*o0[0] + o0[1]*o0[1] + o0[2]*o0[2];
        float i0 = 1.0f / (sqrtf(s0 + 1e-8f) + 1e-10f);
        o0[0] *= i0; o0[1] *= i0; o0[2] *= i0;

        s_rot[0] = o0[0];  s_rot[1] = o0[1];  s_rot[2] = o0[2];
        s_rot[3] = r90[0]; s_rot[4] = r90[1]; s_rot[5] = r90[2];
        s_rot[6] = nv[0];  s_rot[7] = nv[1];  s_rot[8] = nv[2];

#pragma unroll
        for (int d = 0; d < 3; d++) {
            out[OFF_ORIS + p * 3 + d] = ov[d];
            out[OFF_NORS + p * 3 + d] = nv[d];
        }
        s_c2 = s_center[0]*s_center[0] + s_center[1]*s_center[1] + s_center[2]*s_center[2];
    }
    __syncthreads();

    // ---- ball query: 1024-bit mask via ballot ------------------------------
    const float cx = s_center[0], cy = s_center[1], cz = s_center[2];
    const float c2 = s_c2;
    const float* xb = xyz + b * 3 * NPTS;
#pragma unroll
    for (int seg = 0; seg < 8; seg++) {
        int j = seg * 128 + t;
        float px = __ldg(&xb[j]);
        float py = __ldg(&xb[NPTS + j]);
        float pz = __ldg(&xb[2 * NPTS + j]);
        float dot = cx * px + cy * py + cz * pz;
        float d = -2.0f * dot + c2 + (px * px + py * py + pz * pz);
        unsigned m = __ballot_sync(0xffffffffu, !(d > 0.09f));
        if (lane == 0) s_mask[seg * 4 + warp] = m;
    }
    __syncthreads();

    // ---- extract first <=48 set bits in ascending order (warp 0) ----------
    if (warp == 0) {
        unsigned m = s_mask[lane];
        int pc = __popc(m);
        int incl = pc;
#pragma unroll
        for (int o = 1; o < 32; o <<= 1) {
            int v = __shfl_up_sync(0xffffffffu, incl, o);
            if (lane >= o) incl += v;
        }
        int excl = incl - pc;
        if (lane == 31) s_cnt = (incl < NS) ? incl : NS;
        unsigned mm = m;
        int r = excl;
        while (mm && r < NS) {
            int bpos = __ffs(mm) - 1;
            s_nbr[r] = (lane << 5) + bpos;
            mm &= mm - 1;
            r++;
        }
    }
    __syncthreads();

    // ---- pad, local coords, cell index, last-wins winner -------------------
    if (t < NS) {
        int j = (t < s_cnt) ? s_nbr[t] : s_nbr[0];
        s_nbr[t] = j;
        float lx = __ldg(&xb[j]) - cx;
        float ly = __ldg(&xb[NPTS + j]) - cy;
        float lz = __ldg(&xb[2 * NPTS + j]) - cz;
        int c[3];
#pragma unroll
        for (int d = 0; d < 3; d++) {
            float lp = lx * s_rot[d * 3 + 0] + ly * s_rot[d * 3 + 1] + lz * s_rot[d * 3 + 2];
            float v = rintf((lp + 0.3f) / 0.6f * 6.0f);
            int ci = (int)v;
            ci = ci < 0 ? 0 : (ci > 6 ? 6 : ci);
            c[d] = ci;
        }
        int cell = c[0] * 7 + c[1] * 7 + c[2];   // reference quirk: both *g
        s_cell[t] = cell;
        atomicMax(&s_win[cell], t);
    }
    __syncthreads();

    // ---- sparse feat_off: per winning cell, 128-dot x3 against W_unet ------
    // lane handles 4 consecutive channels via one float4 gather.
    for (int s = warp; s < NS; s += 4) {
        int cell = s_cell[s];
        if (s_win[cell] != s) continue;          // warp-uniform
        const float4* f4 = (const float4*)(feat + (((b << 10) + s_nbr[s]) << 7));
        float4 v = __ldg(&f4[lane]);
        int k  = cell % 7;
        int p5 = (cell / 49) * 7 + (cell / 7) % 7;
        const float* wb = Wu + (lane * 4) * 21 + k * 3;
        float a0 = v.x * __ldg(&wb[0])  + v.y * __ldg(&wb[21])
                 + v.z * __ldg(&wb[42]) + v.w * __ldg(&wb[63]);
        float a1 = v.x * __ldg(&wb[1])  + v.y * __ldg(&wb[22])
                 + v.z * __ldg(&wb[43]) + v.w * __ldg(&wb[64]);
        float a2 = v.x * __ldg(&wb[2])  + v.y * __ldg(&wb[23])
                 + v.z * __ldg(&wb[44]) + v.w * __ldg(&wb[65]);
        a0 = wredf(a0); a1 = wredf(a1); a2 = wredf(a2);
        if (lane == 0) {
            atomicAdd(&s_off[p5 * 3 + 0], a0);
            atomicAdd(&s_off[p5 * 3 + 1], a1);
            atomicAdd(&s_off[p5 * 3 + 2], a2);
        }
    }
    __syncthreads();

    // ---- up = vals + feat_off; rotate back to world; write outputs --------
    if (t < 49) {
        int s = t;
        float u0 = (float)(s / 7 - 3) * 0.1f + s_off[s * 3 + 0];
        float u1 = (float)(s % 7 - 3) * 0.1f + s_off[s * 3 + 1];
        float u2 = s_off[s * 3 + 2];
        float w[3];
#pragma unroll
        for (int d = 0; d < 3; d++)
            w[d] = u0 * s_rot[d] + u1 * s_rot[3 + d] + u2 * s_rot[6 + d] + s_center[d];

        float* o_up = out + OFF_PTSUP + (p * 49 + s) * 3;
        o_up[0] = w[0]; o_up[1] = w[1]; o_up[2] = w[2];

        if (s == 24) {
            float* o_of = out + OFF_OFFSET + p * 3;
            o_of[0] = w[0]; o_of[1] = w[1]; o_of[2] = w[2];
        }
#pragma unroll
        for (int q = 0; q < 16; q++) {
            if (s_idx[q] == s) {
                float* o_u = out + OFF_UPS + (p * 16 + q) * 3;
                o_u[0] = w[0]; o_u[1] = w[1]; o_u[2] = w[2];
            }
        }
    }
}

extern "C" void kernel_launch(void* const* d_in, const int* in_sizes, int n_in,
                              void* d_out, int out_size)
{
    const float* xyz   = (const float*)d_in[0];
    const float* feat  = (const float*)d_in[1];
    const float* W0    = (const float*)d_in[2];
    const float* b0    = (const float*)d_in[3];
    const float* W1    = (const float*)d_in[4];
    const float* b1    = (const float*)d_in[5];
    const float* Wu    = (const float*)d_in[6];
    const int*   index = (const int*)d_in[7];
    float* out = (float*)d_out;

    ipunet_kernel<<<2048, 128>>>(xyz, feat, W0, b0, W1, b1, Wu, index, out);
}

// round 3
// speedup vs baseline: 1.6780x; 1.1186x over previous
#include <cuda_runtime.h>

// iPUNet forward, fully fused. One CTA (128 threads) per point, BN=2048 CTAs.
// Phase-overlapped single-wave design:
//  - ball query + oris/nors matvec merged (one load burst, one barrier)
//  - rotation (t==32) runs concurrently with neighbor extraction (warp 0)
//  - winner list compacted; feature gather software-pipelined (1-ahead prefetch)
//
// Shapes: B=2, N=1024, FEAT=128, NSAMPLE=48, GRID=7, RADIUS=0.3
// Output (f32, 417792 elems):
//   oris [0,6144) | nors [6144,12288) | pts_ups [12288,110592)
//   pts_offset [110592,116736) | pts_up [116736,417792)

#define NPTS   1024
#define FEATD  128
#define NS     48

#define OFF_ORIS   0
#define OFF_NORS   6144
#define OFF_UPS    12288
#define OFF_OFFSET 110592
#define OFF_PTSUP  116736

__device__ __forceinline__ float wredf(float x) {
#pragma unroll
    for (int o = 16; o; o >>= 1) x += __shfl_xor_sync(0xffffffffu, x, o);
    return x;
}

__global__ __launch_bounds__(128)
void ipunet_kernel(const float* __restrict__ xyz,
                   const float* __restrict__ feat,
                   const float* __restrict__ W0, const float* __restrict__ b0,
                   const float* __restrict__ W1, const float* __restrict__ b1,
                   const float* __restrict__ Wu, const int* __restrict__ g_index,
                   float* __restrict__ out)
{
    const int p    = blockIdx.x;       // global point id 0..2047
    const int b    = p >> 10;
    const int pid  = p & 1023;
    const int t    = threadIdx.x;      // 0..127
    const int lane = t & 31;
    const int warp = t >> 5;           // 0..3

    __shared__ float    s_rot[9];
    __shared__ float    s_part[4][6];
    __shared__ unsigned s_mask[32];
    __shared__ int      s_nbr[NS];
    __shared__ int      s_win[91];
    __shared__ int      s_cnt;
    __shared__ int      s_nwin;
    __shared__ int      s_wlist[NS];   // packed (cell<<10)|nbr
    __shared__ float    s_off[49 * 3];
    __shared__ int      s_idx[16];

    // ---- broadcast center via direct loads (no staging) --------------------
    const float* xb = xyz + b * 3 * NPTS;
    const float cx = __ldg(&xb[pid]);
    const float cy = __ldg(&xb[NPTS + pid]);
    const float cz = __ldg(&xb[2 * NPTS + pid]);
    const float c2 = cx * cx + cy * cy + cz * cz;

    // ---- smem init ----------------------------------------------------------
    if (t < 16) s_idx[t] = __ldg(&g_index[t]);
    if (t < 91) s_win[t] = -1;
    if (t == 0) s_nwin = 0;
    if (t < 128) {            // zero 147 floats: 128 + 19
        s_off[t] = 0.0f;
        if (t < 19) s_off[128 + t] = 0.0f;
    }

    // ---- merged: ball query (8 segs) + oris/nors matvec --------------------
    {
        // matvec loads issue alongside the distance loads (high MLP region)
        float f  = __ldg(&feat[(p << 7) + t]);
        float w0a = __ldg(&W0[t]),       w0b = __ldg(&W0[128 + t]), w0c = __ldg(&W0[256 + t]);
        float w1a = __ldg(&W1[t]),       w1b = __ldg(&W1[128 + t]), w1c = __ldg(&W1[256 + t]);

#pragma unroll
        for (int seg = 0; seg < 8; seg++) {
            int j = seg * 128 + t;
            float px = __ldg(&xb[j]);
            float py = __ldg(&xb[NPTS + j]);
            float pz = __ldg(&xb[2 * NPTS + j]);
            float d = -2.0f * (cx * px + cy * py + cz * pz) + c2
                      + (px * px + py * py + pz * pz);
            unsigned m = __ballot_sync(0xffffffffu, !(d > 0.09f));
            if (lane == 0) s_mask[seg * 4 + warp] = m;
        }

        float q0 = wredf(f * w0a), q1 = wredf(f * w0b), q2 = wredf(f * w0c);
        float q3 = wredf(f * w1a), q4 = wredf(f * w1b), q5 = wredf(f * w1c);
        if (lane == 0) {
            s_part[warp][0] = q0; s_part[warp][1] = q1; s_part[warp][2] = q2;
            s_part[warp][3] = q3; s_part[warp][4] = q4; s_part[warp][5] = q5;
        }
    }
    __syncthreads();

    // ---- concurrent: rotation on t==32, extraction on warp 0 ---------------
    if (t == 32) {
        float ov[3], nv[3];
#pragma unroll
        for (int d = 0; d < 3; d++) {
            ov[d] = s_part[0][d]   + s_part[1][d]   + s_part[2][d]   + s_part[3][d]   + __ldg(&b0[d]);
            nv[d] = s_part[0][3+d] + s_part[1][3+d] + s_part[2][3+d] + s_part[3][3+d] + __ldg(&b1[d]);
        }
        float io = 1.0f / (sqrtf(ov[0]*ov[0]+ov[1]*ov[1]+ov[2]*ov[2] + 1e-8f) + 1e-10f);
        ov[0] *= io; ov[1] *= io; ov[2] *= io;
        float in = 1.0f / (sqrtf(nv[0]*nv[0]+nv[1]*nv[1]+nv[2]*nv[2] + 1e-8f) + 1e-10f);
        nv[0] *= in; nv[1] *= in; nv[2] *= in;

        float r90[3];
        r90[0] = ov[1]*nv[2] - ov[2]*nv[1];
        r90[1] = ov[2]*nv[0] - ov[0]*nv[2];
        r90[2] = ov[0]*nv[1] - ov[1]*nv[0];
        float ir = 1.0f / (sqrtf(r90[0]*r90[0]+r90[1]*r90[1]+r90[2]*r90[2] + 1e-8f) + 1e-10f);
        r90[0] *= ir; r90[1] *= ir; r90[2] *= ir;

        float o0[3];
        o0[0] = r90[1]*nv[2] - r90[2]*nv[1];
        o0[1] = r90[2]*nv[0] - r90[0]*nv[2];
        o0[2] = r90[0]*nv[1] - r90[1]*nv[0];
        float i0 = 1.0f / (sqrtf(o0[0]*o0[0]+o0[1]*o0[1]+o0[2]*o0[2] + 1e-8f) + 1e-10f);
        o0[0] *= i0; o0[1] *= i0; o0[2] *= i0;

        s_rot[0] = o0[0];  s_rot[1] = o0[1];  s_rot[2] = o0[2];
        s_rot[3] = r90[0]; s_rot[4] = r90[1]; s_rot[5] = r90[2];
        s_rot[6] = nv[0];  s_rot[7] = nv[1];  s_rot[8] = nv[2];

#pragma unroll
        for (int d = 0; d < 3; d++) {
            out[OFF_ORIS + p * 3 + d] = ov[d];
            out[OFF_NORS + p * 3 + d] = nv[d];
        }
    }
    if (warp == 0) {
        unsigned m = s_mask[lane];
        int pc = __popc(m);
        int incl = pc;
#pragma unroll
        for (int o = 1; o < 32; o <<= 1) {
            int v = __shfl_up_sync(0xffffffffu, incl, o);
            if (lane >= o) incl += v;
        }
        int excl = incl - pc;
        if (lane == 31) s_cnt = (incl < NS) ? incl : NS;
        unsigned mm = m;
        int r = excl;
        while (mm && r < NS) {
            int bpos = __ffs(mm) - 1;
            s_nbr[r] = (lane << 5) + bpos;
            mm &= mm - 1;
            r++;
        }
    }
    __syncthreads();

    // ---- local coords -> cell; last-wins winner; compact --------------------
    int myCell = -1, myJ = 0;
    if (t < NS) {
        myJ = (t < s_cnt) ? s_nbr[t] : s_nbr[0];
        float lx = __ldg(&xb[myJ]) - cx;
        float ly = __ldg(&xb[NPTS + myJ]) - cy;
        float lz = __ldg(&xb[2 * NPTS + myJ]) - cz;
        int c[3];
#pragma unroll
        for (int d = 0; d < 3; d++) {
            float lp = lx * s_rot[d*3+0] + ly * s_rot[d*3+1] + lz * s_rot[d*3+2];
            float v = rintf((lp + 0.3f) / 0.6f * 6.0f);
            int ci = (int)v;
            ci = ci < 0 ? 0 : (ci > 6 ? 6 : ci);
            c[d] = ci;
        }
        myCell = c[0] * 7 + c[1] * 7 + c[2];   // reference quirk: both *g
        atomicMax(&s_win[myCell], t);
    }
    __syncthreads();
    if (t < NS && s_win[myCell] == t) {
        int w = atomicAdd(&s_nwin, 1);
        s_wlist[w] = (myCell << 10) | myJ;
    }
    __syncthreads();

    // ---- sparse feat_off: compacted winners, 1-ahead prefetch ---------------
    {
        const int nw = s_nwin;
        const float4* fb = (const float4*)(feat + ((long)b << 17));
        int i = warp;
        float4 v = make_float4(0.f, 0.f, 0.f, 0.f);
        int cell = 0;
        if (i < nw) {
            int pk = s_wlist[i];
            cell = pk >> 10;
            v = __ldg(&fb[((pk & 1023) << 5) + lane]);
        }
        while (i < nw) {
            int inext = i + 4;
            float4 vn = v; int celln = cell;
            if (inext < nw) {
                int pk = s_wlist[inext];
                celln = pk >> 10;
                vn = __ldg(&fb[((pk & 1023) << 5) + lane]);
            }
            int k  = cell % 7;
            int p5 = (cell / 49) * 7 + (cell / 7) % 7;
            const float* wb = Wu + lane * 84 + k * 3;   // lane*4 channels * 21
            float a0 = v.x * __ldg(wb+0)  + v.y * __ldg(wb+21)
                     + v.z * __ldg(wb+42) + v.w * __ldg(wb+63);
            float a1 = v.x * __ldg(wb+1)  + v.y * __ldg(wb+22)
                     + v.z * __ldg(wb+43) + v.w * __ldg(wb+64);
            float a2 = v.x * __ldg(wb+2)  + v.y * __ldg(wb+23)
                     + v.z * __ldg(wb+44) + v.w * __ldg(wb+65);
            a0 = wredf(a0); a1 = wredf(a1); a2 = wredf(a2);
            if (lane == 0) {
                atomicAdd(&s_off[p5 * 3 + 0], a0);
                atomicAdd(&s_off[p5 * 3 + 1], a1);
                atomicAdd(&s_off[p5 * 3 + 2], a2);
            }
            v = vn; cell = celln; i = inext;
        }
    }
    __syncthreads();

    // ---- up = vals + feat_off; rotate back; write outputs -------------------
    if (t < 49) {
        int s = t;
        float u0 = (float)(s / 7 - 3) * 0.1f + s_off[s * 3 + 0];
        float u1 = (float)(s % 7 - 3) * 0.1f + s_off[s * 3 + 1];
        float u2 = s_off[s * 3 + 2];
        float w[3];
#pragma unroll
        for (int d = 0; d < 3; d++)
            w[d] = u0 * s_rot[d] + u1 * s_rot[3 + d] + u2 * s_rot[6 + d]
                 + (d == 0 ? cx : (d == 1 ? cy : cz));

        float* o_up = out + OFF_PTSUP + (p * 49 + s) * 3;
        o_up[0] = w[0]; o_up[1] = w[1]; o_up[2] = w[2];

        if (s == 24) {
            float* o_of = out + OFF_OFFSET + p * 3;
            o_of[0] = w[0]; o_of[1] = w[1]; o_of[2] = w[2];
        }
#pragma unroll
        for (int q = 0; q < 16; q++) {
            if (s_idx[q] == s) {
                float* o_u = out + OFF_UPS + (p * 16 + q) * 3;
                o_u[0] = w[0]; o_u[1] = w[1]; o_u[2] = w[2];
            }
        }
    }
}

extern "C" void kernel_launch(void* const* d_in, const int* in_sizes, int n_in,
                              void* d_out, int out_size)
{
    const float* xyz   = (const float*)d_in[0];
    const float* feat  = (const float*)d_in[1];
    const float* W0    = (const float*)d_in[2];
    const float* b0    = (const float*)d_in[3];
    const float* W1    = (const float*)d_in[4];
    const float* b1    = (const float*)d_in[5];
    const float* Wu    = (const float*)d_in[6];
    const int*   index = (const int*)d_in[7];
    float* out = (float*)d_out;

    ipunet_kernel<<<2048, 128>>>(xyz, feat, W0, b0, W1, b1, Wu, index, out);
}